// round 8
// baseline (speedup 1.0000x reference)
#include <cuda_runtime.h>
#include <cuda_fp16.h>
#include <cstdint>

// ---------------- problem shapes ----------------
#define Bc   512
#define Sc   64
#define Nc   8
#define Ac   16
#define Hc   256
#define OBSc 512

// smem strides (words)
#define BSTR2 136    // uint32 words per B column (16 chunks * 8 + pad 8)
#define PASTR 264    // floats per PA row (conflict-free phases)
#define XSTR  264    // floats per X row

// ---------------- device scratch ----------------
__device__ __align__(16) uint32_t g_B16[2][128 * BSTR2]; // fp16x2 W2 image per n-half
__device__ __align__(16) float    g_PA2[Bc * 64 * 256];  // PA rows, obs1 folded into u=0

// ---------------- helpers ----------------
// mish(x) = x * (1 - 2/(u^2+1)), u = 1+e^x ; reciprocal via bit-hack + 2 Newton
__device__ __forceinline__ float mish_f(float x) {
    float e  = __expf(fminf(x, 15.0f));
    float u  = 1.0f + e;
    float d  = fmaf(u, u, 1.0f);                 // u^2 + 1  (>= 2)
    float r  = __uint_as_float(0x7EF477D5u - __float_as_uint(d));
    r = r * (2.0f - d * r);
    r = r * (2.0f - d * r);
    return x * (1.0f - 2.0f * r);
}

// pack two f32 -> f16x2 register (lo in low half)
__device__ __forceinline__ uint32_t h2pack(float lo, float hi) {
    uint32_t r;
    asm("cvt.rn.f16x2.f32 %0, %1, %2;" : "=r"(r) : "f"(hi), "f"(lo));
    return r;
}

// m16n8k16 fp16 mma, f32 accumulate; C is a float4 variable (regs only)
#define MMA_F16(C, a0, a1, a2, a3, b0, b1)                                    \
    asm volatile("mma.sync.aligned.m16n8k16.row.col.f32.f16.f16.f32 "        \
        "{%0,%1,%2,%3}, {%4,%5,%6,%7}, {%8,%9}, {%0,%1,%2,%3};"              \
        : "+f"(C.x), "+f"(C.y), "+f"(C.z), "+f"(C.w)                         \
        : "r"(a0), "r"(a1), "r"(a2), "r"(a3), "r"(b0), "r"(b1))

// ================= prep 1: W2 -> fp16x2 packed B images =================
// word layout per column: idx = chunk*8 + 2*tg + hi  (chunk=k>>4, tg=(k>>1)&3, hi=(k>>3)&1)
__global__ void prep_w2_kernel(const float* __restrict__ W2) {
    int idx = blockIdx.x * blockDim.x + threadIdx.x;   // 2*128*128 = 32768 words
    if (idx >= 2 * 128 * 128) return;
    int nhalf = idx >> 14;
    int rem   = idx & 16383;
    int col   = rem >> 7;
    int w     = rem & 127;
    int chunk = w >> 3;
    int tg    = (w >> 1) & 3;
    int hi    = w & 1;
    int k0    = chunk * 16 + hi * 8 + tg * 2;
    int n     = nhalf * 128 + col;
    float lo  = W2[k0 * Hc + n];
    float hif = W2[(k0 + 1) * Hc + n];
    g_B16[nhalf][col * BSTR2 + w] = h2pack(lo, hif);
}

// ================= prep 2: PA rows with obs folded =================
__global__ void __launch_bounds__(256)
prep_obs_pa_kernel(const float* __restrict__ state,
                   const float* __restrict__ action,
                   const float* __restrict__ W1,
                   const float* __restrict__ b1) {
    __shared__ float sState[4 * OBSc];
    __shared__ float sAct[4 * 128];
    const int tid = threadIdx.x;
    const int b0  = blockIdx.x * 4;

    for (int i = tid; i < 4 * OBSc; i += 256) sState[i] = state[b0 * OBSc + i];
    for (int i = tid; i < 4 * 128;  i += 256) sAct[i]   = action[b0 * 128 + i];
    __syncthreads();

    const int h = tid;
    float ob0 = b1[h], ob1 = ob0, ob2 = ob0, ob3 = ob0;
    for (int k = 0; k < OBSc; ++k) {
        float w = __ldg(&W1[k * Hc + h]);
        ob0 = fmaf(sState[k],            w, ob0);
        ob1 = fmaf(sState[OBSc + k],     w, ob1);
        ob2 = fmaf(sState[2 * OBSc + k], w, ob2);
        ob3 = fmaf(sState[3 * OBSc + k], w, ob3);
    }

    for (int j = 0; j < 8; ++j) {
        for (int n = 0; n < 8; ++n) {
            float p0 = 0.f, p1 = 0.f, p2 = 0.f, p3 = 0.f;
            #pragma unroll
            for (int k = 0; k < 16; ++k) {
                float w = __ldg(&W1[(OBSc + j * 16 + k) * Hc + h]);
                p0 = fmaf(sAct[0 * 128 + n * 16 + k], w, p0);
                p1 = fmaf(sAct[1 * 128 + n * 16 + k], w, p1);
                p2 = fmaf(sAct[2 * 128 + n * 16 + k], w, p2);
                p3 = fmaf(sAct[3 * 128 + n * 16 + k], w, p3);
            }
            if (j == 0) { p0 += ob0; p1 += ob1; p2 += ob2; p3 += ob3; }
            g_PA2[((b0 + 0) * 64 + j * 8 + n) * 256 + h] = p0;
            g_PA2[((b0 + 1) * 64 + j * 8 + n) * 256 + h] = p1;
            g_PA2[((b0 + 2) * 64 + j * 8 + n) * 256 + h] = p2;
            g_PA2[((b0 + 3) * 64 + j * 8 + n) * 256 + h] = p3;
        }
    }
}

// ================= main fused kernel =================
// grid 1024: (b = bx>>1, nh = bx&1). 256 threads, 8 warps.
// X[s] holds running prefix. Pass p handles t=2p (X) and t=2p+1 (X + one PA row).
// Warp w, lane-group lam owns s = w*8 + lam.
#define OFF_B    0
#define SZ_B     (128 * BSTR2 * 4)         // 69632
#define OFF_PA   (OFF_B + SZ_B)
#define SZ_PA    (64 * PASTR * 4)          // 67584
#define OFF_X    (OFF_PA + SZ_PA)
#define SZ_X     (64 * XSTR * 4)           // 67584
#define OFF_PERM (OFF_X + SZ_X)            // 512 ints
#define OFF_ROWQ (OFF_PERM + 2048)         // 512 f
#define OFF_B2   (OFF_ROWQ + 2048)         // 128 f
#define OFF_W3   (OFF_B2 + 512)            // 128 f
#define OFF_RED  (OFF_W3 + 512)            // 256 f
#define SMEM_MAIN (OFF_RED + 1024)         // 210944 B

__global__ void __launch_bounds__(256, 1)
shapley_mma(const float* __restrict__ b2,
            const float* __restrict__ W3,
            const float* __restrict__ b3,
            const int*   __restrict__ perm,
            float*       __restrict__ out) {
    extern __shared__ char smem[];
    const int tid  = threadIdx.x;
    const int wid  = tid >> 5;
    const int lane = tid & 31;
    const int b    = blockIdx.x >> 1;
    const int nh   = blockIdx.x & 1;

    uint32_t* sB  = (uint32_t*)(smem + OFF_B);
    float* sPA   = (float*)(smem + OFF_PA);
    float* sX    = (float*)(smem + OFF_X);
    int*   sPerm = (int*)  (smem + OFF_PERM);
    float* sRowQ = (float*)(smem + OFF_ROWQ);
    float* sB2   = (float*)(smem + OFF_B2);
    float* sW3   = (float*)(smem + OFF_W3);
    float* sRed  = (float*)(smem + OFF_RED);

    // ---- stage B (69632 B linear) ----
    {
        const uint4* src = (const uint4*)g_B16[nh];
        uint4* dst = (uint4*)sB;
        for (int i = tid; i < (128 * BSTR2) / 4; i += 256) dst[i] = src[i];
    }
    // ---- stage PA (float4 rows into stride-264 layout) ----
    {
        const float4* src = (const float4*)(g_PA2 + b * (64 * 256));
        for (int idx = tid; idx < 64 * 64; idx += 256) {
            int r = idx >> 6, c = idx & 63;
            *(float4*)&sPA[r * PASTR + c * 4] = src[idx];
        }
    }
    for (int i = tid; i < Sc * Nc; i += 256) sPerm[i] = perm[b * (Sc * Nc) + i];
    if (tid < 128) {
        sB2[tid] = b2[nh * 128 + tid];
        sW3[tid] = W3[nh * 128 + tid];
    }
    const float b3v = b3[0];
    __syncthreads();

    // ---- init X[s] = PA row pi(s,0) (obs folded into u=0 rows) ----
    {
        const int su = tid >> 2, q = tid & 3;
        const int r0 = sPerm[su * 8] * PASTR;          // u=0 block: row = pi
        #pragma unroll
        for (int i = 0; i < 16; ++i) {
            float4 v = *(const float4*)&sPA[r0 + q * 64 + i * 4];
            *(float4*)&sX[su * XSTR + q * 64 + i * 4] = v;
        }
    }
    __syncthreads();

    const int lam = lane >> 2;    // fragment row group (0..7)
    const int kq  = lane & 3;     // fragment k sub-index (0..3)
    const int s   = wid * 8 + lam;
    const int xb  = s * XSTR;

    #pragma unroll 1
    for (int p = 0; p < 4; ++p) {
        // PA row for t = 2p+1
        const int rbB = ((2 * p + 1) * 8 + sPerm[s * 8 + 2 * p + 1]) * PASTR;

        float4 C0  = {0,0,0,0}, C1  = {0,0,0,0}, C2  = {0,0,0,0}, C3  = {0,0,0,0};
        float4 C4  = {0,0,0,0}, C5  = {0,0,0,0}, C6  = {0,0,0,0}, C7  = {0,0,0,0};
        float4 C8  = {0,0,0,0}, C9  = {0,0,0,0}, C10 = {0,0,0,0}, C11 = {0,0,0,0};
        float4 C12 = {0,0,0,0}, C13 = {0,0,0,0}, C14 = {0,0,0,0}, C15 = {0,0,0,0};

        #pragma unroll 2
        for (int ch = 0; ch < 16; ++ch) {
            const int kb = ch * 16 + 2 * kq;
            float2 xa0 = *(const float2*)&sX[xb + kb];
            float2 xa8 = *(const float2*)&sX[xb + kb + 8];
            float2 pb0 = *(const float2*)&sPA[rbB + kb];
            float2 pb8 = *(const float2*)&sPA[rbB + kb + 8];
            const uint32_t a0 = h2pack(mish_f(xa0.x), mish_f(xa0.y));
            const uint32_t a2 = h2pack(mish_f(xa8.x), mish_f(xa8.y));
            const uint32_t a1 = h2pack(mish_f(xa0.x + pb0.x), mish_f(xa0.y + pb0.y));
            const uint32_t a3 = h2pack(mish_f(xa8.x + pb8.x), mish_f(xa8.y + pb8.y));
            const int bof = ch * 8 + 2 * kq;
#define BMMA(nt) { uint2 bb = *(const uint2*)&sB[((nt) * 8 + lam) * BSTR2 + bof]; \
                   MMA_F16(C##nt, a0, a1, a2, a3, bb.x, bb.y); }
            BMMA(0)  BMMA(1)  BMMA(2)  BMMA(3)
            BMMA(4)  BMMA(5)  BMMA(6)  BMMA(7)
            BMMA(8)  BMMA(9)  BMMA(10) BMMA(11)
            BMMA(12) BMMA(13) BMMA(14) BMMA(15)
#undef BMMA
        }

        // ---- epilogue: mish(z+b2)*w3, row-sum over this CTA's 128 cols ----
        float rs0 = 0.f, rs1 = 0.f;
#define EPI(nt) { const int c0 = (nt) * 8 + kq * 2;                               \
    rs0 += mish_f(C##nt.x + sB2[c0])     * sW3[c0]                                \
         + mish_f(C##nt.y + sB2[c0 + 1]) * sW3[c0 + 1];                           \
    rs1 += mish_f(C##nt.z + sB2[c0])     * sW3[c0]                                \
         + mish_f(C##nt.w + sB2[c0 + 1]) * sW3[c0 + 1]; }
        EPI(0)  EPI(1)  EPI(2)  EPI(3)
        EPI(4)  EPI(5)  EPI(6)  EPI(7)
        EPI(8)  EPI(9)  EPI(10) EPI(11)
        EPI(12) EPI(13) EPI(14) EPI(15)
#undef EPI
        rs0 += __shfl_xor_sync(0xffffffffu, rs0, 1);
        rs0 += __shfl_xor_sync(0xffffffffu, rs0, 2);
        rs1 += __shfl_xor_sync(0xffffffffu, rs1, 1);
        rs1 += __shfl_xor_sync(0xffffffffu, rs1, 2);
        if (kq == 0) {
            sRowQ[(2 * p)     * 64 + s] = rs0 + 0.5f * b3v;   // t = 2p
            sRowQ[(2 * p + 1) * 64 + s] = rs1 + 0.5f * b3v;   // t = 2p+1
        }

        // ---- boundary: X += PA[pi(2p+1)] + PA[pi(2p+2)] ----
        if (p < 3) {
            __syncthreads();   // all MMA reads of X done
            const int su = tid >> 2, q = tid & 3;
            const int r1 = ((2 * p + 1) * 8 + sPerm[su * 8 + 2 * p + 1]) * PASTR;
            const int r2 = ((2 * p + 2) * 8 + sPerm[su * 8 + 2 * p + 2]) * PASTR;
            #pragma unroll
            for (int i = 0; i < 16; ++i) {
                const int o = q * 64 + i * 4;
                float4 x = *(const float4*)&sX[su * XSTR + o];
                float4 u = *(const float4*)&sPA[r1 + o];
                float4 v = *(const float4*)&sPA[r2 + o];
                x.x += u.x + v.x; x.y += u.y + v.y;
                x.z += u.z + v.z; x.w += u.w + v.w;
                *(float4*)&sX[su * XSTR + o] = x;
            }
            __syncthreads();   // X ready for next pass
        }
    }
    __syncthreads();

    // ---- gather q1 partials: (s,i) -> row = perm[s,i]*64 + s ----
    {
        const int i = tid & 7, su = tid >> 3;
        int t0 = sPerm[su * 8 + i];
        int t1 = sPerm[(su + 32) * 8 + i];
        sRed[tid] = sRowQ[t0 * 64 + su] + sRowQ[t1 * 64 + su + 32];
    }
    __syncthreads();
    if (tid < 8) {
        float sum = 0.0f;
        #pragma unroll 8
        for (int g = 0; g < 32; ++g) sum += sRed[g * 8 + tid];
        atomicAdd(&out[b * Nc + tid], sum * (1.0f / 64.0f));
    }
}

// duplicate q1 into second half of the output tuple
__global__ void dup_out_kernel(float* __restrict__ out) {
    int i = blockIdx.x * blockDim.x + threadIdx.x;
    if (i < Bc * Nc) out[Bc * Nc + i] = out[i];
}

extern "C" void kernel_launch(void* const* d_in, const int* in_sizes, int n_in,
                              void* d_out, int out_size) {
    const float* state  = (const float*)d_in[0];
    const float* action = (const float*)d_in[1];
    const float* W1     = (const float*)d_in[2];
    const float* b1     = (const float*)d_in[3];
    const float* W2     = (const float*)d_in[4];
    const float* b2     = (const float*)d_in[5];
    const float* W3     = (const float*)d_in[6];
    const float* b3     = (const float*)d_in[7];
    const int*   perm   = (const int*)  d_in[8];
    float* out = (float*)d_out;

    cudaFuncSetAttribute(shapley_mma,
                         cudaFuncAttributeMaxDynamicSharedMemorySize, SMEM_MAIN);

    prep_w2_kernel<<<128, 256>>>(W2);
    prep_obs_pa_kernel<<<128, 256>>>(state, action, W1, b1);

    int zelems = (out_size < Bc * Nc) ? out_size : (Bc * Nc);
    cudaMemsetAsync(d_out, 0, (size_t)zelems * sizeof(float), 0);

    shapley_mma<<<Bc * 2, 256, SMEM_MAIN>>>(b2, W3, b3, perm, out);

    if (out_size >= 2 * Bc * Nc)
        dup_out_kernel<<<(Bc * Nc + 255) / 256, 256>>>(out);
}

// round 9
// speedup vs baseline: 1.4189x; 1.4189x over previous
#include <cuda_runtime.h>
#include <cuda_fp16.h>
#include <cstdint>

// ---------------- problem shapes ----------------
#define Bc   512
#define Sc   64
#define Nc   8
#define Ac   16
#define Hc   256
#define OBSc 512

// smem strides (words)
#define BSTR2 136    // uint32 words per B column (16 chunks * 8 + pad 8)
#define PAHW  136    // uint32 words per PA row (128 data + 8 pad)

// ---------------- device scratch ----------------
__device__ __align__(16) uint32_t g_B16[2][128 * BSTR2]; // fp16x2 W2 image per n-half
__device__ __align__(16) uint32_t g_PAh[Bc * 64 * 128];  // fp16x2 PA rows, obs folded in u=0

// ---------------- helpers ----------------
// mish(x) = x * (1 - 2/(u^2+1)), u = 1+e^x ; reciprocal via bit-hack + 2 Newton
__device__ __forceinline__ float mish_f(float x) {
    float e  = __expf(fminf(x, 15.0f));
    float u  = 1.0f + e;
    float d  = fmaf(u, u, 1.0f);                 // u^2 + 1  (>= 2)
    float r  = __uint_as_float(0x7EF477D5u - __float_as_uint(d));
    r = r * (2.0f - d * r);
    r = r * (2.0f - d * r);
    return x * (1.0f - 2.0f * r);
}

// pack two f32 -> f16x2 register (lo in low half)
__device__ __forceinline__ uint32_t h2pack(float lo, float hi) {
    uint32_t r;
    asm("cvt.rn.f16x2.f32 %0, %1, %2;" : "=r"(r) : "f"(hi), "f"(lo));
    return r;
}
__device__ __forceinline__ float2 h22f2(uint32_t w) {
    __half2 h = *(__half2*)&w;
    return __half22float2(h);
}

// m16n8k16 fp16 mma, f32 accumulate; C is a float4 variable (regs only)
#define MMA_F16(C, a0, a1, a2, a3, b0, b1)                                    \
    asm volatile("mma.sync.aligned.m16n8k16.row.col.f32.f16.f16.f32 "        \
        "{%0,%1,%2,%3}, {%4,%5,%6,%7}, {%8,%9}, {%0,%1,%2,%3};"              \
        : "+f"(C.x), "+f"(C.y), "+f"(C.z), "+f"(C.w)                         \
        : "r"(a0), "r"(a1), "r"(a2), "r"(a3), "r"(b0), "r"(b1))

// ================= prep 1: W2 -> fp16x2 packed B images =================
// word layout per column: idx = chunk*8 + 2*tg + hi  (chunk=k>>4, tg=(k>>1)&3, hi=(k>>3)&1)
__global__ void prep_w2_kernel(const float* __restrict__ W2) {
    int idx = blockIdx.x * blockDim.x + threadIdx.x;   // 2*128*128 = 32768 words
    if (idx >= 2 * 128 * 128) return;
    int nhalf = idx >> 14;
    int rem   = idx & 16383;
    int col   = rem >> 7;
    int w     = rem & 127;
    int chunk = w >> 3;
    int tg    = (w >> 1) & 3;
    int hi    = w & 1;
    int k0    = chunk * 16 + hi * 8 + tg * 2;
    int n     = nhalf * 128 + col;
    float lo  = W2[k0 * Hc + n];
    float hif = W2[(k0 + 1) * Hc + n];
    g_B16[nhalf][col * BSTR2 + w] = h2pack(lo, hif);
}

// ================= prep 2: PA rows (obs folded) -> fp16x2 words =================
__global__ void __launch_bounds__(256)
prep_obs_pa_kernel(const float* __restrict__ state,
                   const float* __restrict__ action,
                   const float* __restrict__ W1,
                   const float* __restrict__ b1) {
    __shared__ float sState[4 * OBSc];
    __shared__ float sAct[4 * 128];
    __shared__ float sT[4 * 256];
    const int tid = threadIdx.x;
    const int b0  = blockIdx.x * 4;

    for (int i = tid; i < 4 * OBSc; i += 256) sState[i] = state[b0 * OBSc + i];
    for (int i = tid; i < 4 * 128;  i += 256) sAct[i]   = action[b0 * 128 + i];
    __syncthreads();

    const int h = tid;
    float ob0 = b1[h], ob1 = ob0, ob2 = ob0, ob3 = ob0;
    for (int k = 0; k < OBSc; ++k) {
        float w = __ldg(&W1[k * Hc + h]);
        ob0 = fmaf(sState[k],            w, ob0);
        ob1 = fmaf(sState[OBSc + k],     w, ob1);
        ob2 = fmaf(sState[2 * OBSc + k], w, ob2);
        ob3 = fmaf(sState[3 * OBSc + k], w, ob3);
    }

    for (int j = 0; j < 8; ++j) {
        for (int n = 0; n < 8; ++n) {
            float p0 = 0.f, p1 = 0.f, p2 = 0.f, p3 = 0.f;
            #pragma unroll
            for (int k = 0; k < 16; ++k) {
                float w = __ldg(&W1[(OBSc + j * 16 + k) * Hc + h]);
                p0 = fmaf(sAct[0 * 128 + n * 16 + k], w, p0);
                p1 = fmaf(sAct[1 * 128 + n * 16 + k], w, p1);
                p2 = fmaf(sAct[2 * 128 + n * 16 + k], w, p2);
                p3 = fmaf(sAct[3 * 128 + n * 16 + k], w, p3);
            }
            if (j == 0) { p0 += ob0; p1 += ob1; p2 += ob2; p3 += ob3; }
            sT[0 * 256 + h] = p0;
            sT[1 * 256 + h] = p1;
            sT[2 * 256 + h] = p2;
            sT[3 * 256 + h] = p3;
            __syncthreads();
            if (tid < 128) {
                #pragma unroll
                for (int q = 0; q < 4; ++q) {
                    uint32_t w = h2pack(sT[q * 256 + 2 * tid],
                                        sT[q * 256 + 2 * tid + 1]);
                    g_PAh[((b0 + q) * 64 + j * 8 + n) * 128 + tid] = w;
                }
            }
            __syncthreads();
        }
    }
}

// ================= main fused kernel =================
// grid 1024: (b = bx>>1, nh = bx&1). 256 threads, 8 warps, 2 CTAs/SM.
// rows r = t*64 + s. Warp tile: 16 rows x 128 cols; 4 passes; K chunks of 16.
#define OFF_B    0
#define SZ_B     (128 * BSTR2 * 4)         // 69632
#define OFF_PAH  (OFF_B + SZ_B)
#define SZ_PAH   (64 * PAHW * 4)           // 34816
#define OFF_PERM (OFF_PAH + SZ_PAH)        // 512 ints
#define OFF_ROWQ (OFF_PERM + 2048)         // 512 f
#define OFF_B2   (OFF_ROWQ + 2048)         // 128 f
#define OFF_W3   (OFF_B2 + 512)            // 128 f
#define OFF_RED  (OFF_W3 + 512)            // 256 f
#define SMEM_MAIN (OFF_RED + 1024)         // 110592 B -> 2 CTAs/SM

__global__ void __launch_bounds__(256, 2)
shapley_mma(const float* __restrict__ b2,
            const float* __restrict__ W3,
            const float* __restrict__ b3,
            const int*   __restrict__ perm,
            float*       __restrict__ out) {
    extern __shared__ char smem[];
    const int tid  = threadIdx.x;
    const int wid  = tid >> 5;
    const int lane = tid & 31;
    const int b    = blockIdx.x >> 1;
    const int nh   = blockIdx.x & 1;

    uint32_t* sB   = (uint32_t*)(smem + OFF_B);
    uint32_t* sPAh = (uint32_t*)(smem + OFF_PAH);
    int*   sPerm = (int*)  (smem + OFF_PERM);
    float* sRowQ = (float*)(smem + OFF_ROWQ);
    float* sB2   = (float*)(smem + OFF_B2);
    float* sW3   = (float*)(smem + OFF_W3);
    float* sRed  = (float*)(smem + OFF_RED);

    // ---- stage B (69632 B linear) ----
    {
        const uint4* src = (const uint4*)g_B16[nh];
        uint4* dst = (uint4*)sB;
        for (int i = tid; i < (128 * BSTR2) / 4; i += 256) dst[i] = src[i];
    }
    // ---- stage PA (fp16x2 words, 128 -> stride-136 rows) ----
    {
        const uint4* src = (const uint4*)(g_PAh + b * (64 * 128));
        for (int idx = tid; idx < 64 * 32; idx += 256) {
            int r = idx >> 5, c = idx & 31;
            *(uint4*)&sPAh[r * PAHW + c * 4] = src[idx];
        }
    }
    for (int i = tid; i < Sc * Nc; i += 256) sPerm[i] = perm[b * (Sc * Nc) + i];
    if (tid < 128) {
        sB2[tid] = b2[nh * 128 + tid];
        sW3[tid] = W3[nh * 128 + tid];
    }
    const float b3v = b3[0];
    __syncthreads();

    const int lam = lane >> 2;    // fragment row group (0..7)
    const int kq  = lane & 3;     // fragment k sub-index (0..3)

    #pragma unroll 1
    for (int p = 0; p < 4; ++p) {
        const int R  = p * 128 + wid * 16;     // first row of warp tile
        const int t  = R >> 6;                 // warp-uniform prefix cutoff (0..7)
        const int sa = (R & 63) + lam;         // s of row lam
        const int sb = sa + 8;                 // s of row lam+8

        int rbA0, rbA1, rbA2, rbA3, rbA4, rbA5, rbA6, rbA7;
        int rbB0, rbB1, rbB2, rbB3, rbB4, rbB5, rbB6, rbB7;
#define RBI(u) rbA##u = (u * 8 + sPerm[sa * 8 + u]) * PAHW; \
               rbB##u = (u * 8 + sPerm[sb * 8 + u]) * PAHW;
        RBI(0) RBI(1) RBI(2) RBI(3) RBI(4) RBI(5) RBI(6) RBI(7)
#undef RBI

        float4 C0  = {0,0,0,0}, C1  = {0,0,0,0}, C2  = {0,0,0,0}, C3  = {0,0,0,0};
        float4 C4  = {0,0,0,0}, C5  = {0,0,0,0}, C6  = {0,0,0,0}, C7  = {0,0,0,0};
        float4 C8  = {0,0,0,0}, C9  = {0,0,0,0}, C10 = {0,0,0,0}, C11 = {0,0,0,0};
        float4 C12 = {0,0,0,0}, C13 = {0,0,0,0}, C14 = {0,0,0,0}, C15 = {0,0,0,0};

        #pragma unroll 1
        for (int ch = 0; ch < 16; ++ch) {
            const int w0 = ch * 8 + kq;        // word = halfs (2w, 2w+1)
            float2 vA0 = h22f2(sPAh[rbA0 + w0]);
            float2 vA8 = h22f2(sPAh[rbA0 + w0 + 4]);
            float2 vB0 = h22f2(sPAh[rbB0 + w0]);
            float2 vB8 = h22f2(sPAh[rbB0 + w0 + 4]);
            float xA0 = vA0.x, xA1 = vA0.y, xA8 = vA8.x, xA9 = vA8.y;
            float xB0 = vB0.x, xB1 = vB0.y, xB8 = vB8.x, xB9 = vB8.y;
#define PSUM(u) if (t >= u) {                                                 \
    float2 wA0 = h22f2(sPAh[rbA##u + w0]);                                    \
    float2 wA8 = h22f2(sPAh[rbA##u + w0 + 4]);                                \
    float2 wB0 = h22f2(sPAh[rbB##u + w0]);                                    \
    float2 wB8 = h22f2(sPAh[rbB##u + w0 + 4]);                                \
    xA0 += wA0.x; xA1 += wA0.y; xA8 += wA8.x; xA9 += wA8.y;                   \
    xB0 += wB0.x; xB1 += wB0.y; xB8 += wB8.x; xB9 += wB8.y; }
            PSUM(1) PSUM(2) PSUM(3) PSUM(4) PSUM(5) PSUM(6) PSUM(7)
#undef PSUM
            const uint32_t a0 = h2pack(mish_f(xA0), mish_f(xA1));
            const uint32_t a1 = h2pack(mish_f(xB0), mish_f(xB1));
            const uint32_t a2 = h2pack(mish_f(xA8), mish_f(xA9));
            const uint32_t a3 = h2pack(mish_f(xB8), mish_f(xB9));
            const int bof = ch * 8 + 2 * kq;
#define BMMA(nt) { uint2 bb = *(const uint2*)&sB[((nt) * 8 + lam) * BSTR2 + bof]; \
                   MMA_F16(C##nt, a0, a1, a2, a3, bb.x, bb.y); }
            BMMA(0)  BMMA(1)  BMMA(2)  BMMA(3)
            BMMA(4)  BMMA(5)  BMMA(6)  BMMA(7)
            BMMA(8)  BMMA(9)  BMMA(10) BMMA(11)
            BMMA(12) BMMA(13) BMMA(14) BMMA(15)
#undef BMMA
        }

        // ---- epilogue: mish(z+b2)*w3, row-sum over this CTA's 128 cols ----
        float rs0 = 0.f, rs1 = 0.f;
#define EPI(nt) { const int c0 = (nt) * 8 + kq * 2;                               \
    rs0 += mish_f(C##nt.x + sB2[c0])     * sW3[c0]                                \
         + mish_f(C##nt.y + sB2[c0 + 1]) * sW3[c0 + 1];                           \
    rs1 += mish_f(C##nt.z + sB2[c0])     * sW3[c0]                                \
         + mish_f(C##nt.w + sB2[c0 + 1]) * sW3[c0 + 1]; }
        EPI(0)  EPI(1)  EPI(2)  EPI(3)
        EPI(4)  EPI(5)  EPI(6)  EPI(7)
        EPI(8)  EPI(9)  EPI(10) EPI(11)
        EPI(12) EPI(13) EPI(14) EPI(15)
#undef EPI
        rs0 += __shfl_xor_sync(0xffffffffu, rs0, 1);
        rs0 += __shfl_xor_sync(0xffffffffu, rs0, 2);
        rs1 += __shfl_xor_sync(0xffffffffu, rs1, 1);
        rs1 += __shfl_xor_sync(0xffffffffu, rs1, 2);
        if (kq == 0) {
            sRowQ[R + lam]     = rs0 + 0.5f * b3v;
            sRowQ[R + lam + 8] = rs1 + 0.5f * b3v;
        }
    }
    __syncthreads();

    // ---- gather q1 partials: (s,i) -> row = perm[s,i]*64 + s ----
    {
        const int i = tid & 7, su = tid >> 3;
        int t0 = sPerm[su * 8 + i];
        int t1 = sPerm[(su + 32) * 8 + i];
        sRed[tid] = sRowQ[t0 * 64 + su] + sRowQ[t1 * 64 + su + 32];
    }
    __syncthreads();
    if (tid < 8) {
        float sum = 0.0f;
        #pragma unroll 8
        for (int g = 0; g < 32; ++g) sum += sRed[g * 8 + tid];
        atomicAdd(&out[b * Nc + tid], sum * (1.0f / 64.0f));
    }
}

// duplicate q1 into second half of the output tuple
__global__ void dup_out_kernel(float* __restrict__ out) {
    int i = blockIdx.x * blockDim.x + threadIdx.x;
    if (i < Bc * Nc) out[Bc * Nc + i] = out[i];
}

extern "C" void kernel_launch(void* const* d_in, const int* in_sizes, int n_in,
                              void* d_out, int out_size) {
    const float* state  = (const float*)d_in[0];
    const float* action = (const float*)d_in[1];
    const float* W1     = (const float*)d_in[2];
    const float* b1     = (const float*)d_in[3];
    const float* W2     = (const float*)d_in[4];
    const float* b2     = (const float*)d_in[5];
    const float* W3     = (const float*)d_in[6];
    const float* b3     = (const float*)d_in[7];
    const int*   perm   = (const int*)  d_in[8];
    float* out = (float*)d_out;

    cudaFuncSetAttribute(shapley_mma,
                         cudaFuncAttributeMaxDynamicSharedMemorySize, SMEM_MAIN);

    prep_w2_kernel<<<128, 256>>>(W2);
    prep_obs_pa_kernel<<<128, 256>>>(state, action, W1, b1);

    int zelems = (out_size < Bc * Nc) ? out_size : (Bc * Nc);
    cudaMemsetAsync(d_out, 0, (size_t)zelems * sizeof(float), 0);

    shapley_mma<<<Bc * 2, 256, SMEM_MAIN>>>(b2, W3, b3, perm, out);

    if (out_size >= 2 * Bc * Nc)
        dup_out_kernel<<<(Bc * Nc + 255) / 256, 256>>>(out);
}